// round 1
// baseline (speedup 1.0000x reference)
#include <cuda_runtime.h>
#include <cstdint>
#include <cstddef>

#define NN 50000
#define NE 1600000
#define LAYERS 3
#define FF 218
#define FFP 224

typedef unsigned long long ULL;

// ---------------- device scratch (no allocs allowed) ----------------
__device__ float g_xs[NN * 256];      // JK concat storage: [emb | h1 | h2 | h3]
__device__ float g_feat[NN * 128];    // per-layer GAT features (also mlp temp)
__device__ float g_gat[NN * 128];     // GAT aggregation output
__device__ float g_ff[NN * FFP];      // ff1 output (padded 218->224)
__device__ float g_mlp[NN * 64];      // ff2 output temp
__device__ float g_el[NN * 2];
__device__ float g_er[NN * 2];
__device__ int   g_rowptr[NN + 1];
__device__ int   g_cursor[NN];
__device__ int   g_srcsorted[NE];
__device__ float g_stats[512];        // [0:256) col sums, [256:512) col sumsq
__device__ float g_scale[256];
__device__ float g_shift[256];

// ---------------- f32x2 packed helpers ----------------
__device__ __forceinline__ ULL pk2(float lo, float hi) {
    ULL r; asm("mov.b64 %0, {%1, %2};" : "=l"(r) : "f"(lo), "f"(hi)); return r;
}
__device__ __forceinline__ void upk2(ULL v, float& lo, float& hi) {
    asm("mov.b64 {%0, %1}, %2;" : "=f"(lo), "=f"(hi) : "l"(v));
}
__device__ __forceinline__ void fma2(ULL& d, ULL a, ULL b) {
    asm("fma.rn.f32x2 %0, %1, %2, %0;" : "+l"(d) : "l"(a), "l"(b));
}

// ---------------- CSR build ----------------
__global__ void hist_kernel(const int* __restrict__ dst) {
    for (int i = blockIdx.x * blockDim.x + threadIdx.x; i < NE; i += gridDim.x * blockDim.x)
        atomicAdd(&g_cursor[dst[i]], 1);
}

__global__ void scan_kernel() {
    __shared__ int ssum[1024];
    const int T = 1024;
    int t = threadIdx.x;
    const int per = (NN + T - 1) / T;
    int b = t * per;
    int e = min(b + per, NN);
    int s = 0;
    for (int i = b; i < e; i++) s += g_cursor[i];
    ssum[t] = s;
    __syncthreads();
    for (int off = 1; off < T; off <<= 1) {
        int v = 0;
        if (t >= off) v = ssum[t - off];
        __syncthreads();
        if (t >= off) ssum[t] += v;
        __syncthreads();
    }
    int run = (t == 0) ? 0 : ssum[t - 1];
    for (int i = b; i < e; i++) {
        int d = g_cursor[i];
        g_rowptr[i] = run;
        g_cursor[i] = run;
        run += d;
    }
    if (t == T - 1) g_rowptr[NN] = run;
}

__global__ void scatter_kernel(const int* __restrict__ src, const int* __restrict__ dst) {
    for (int i = blockIdx.x * blockDim.x + threadIdx.x; i < NE; i += gridDim.x * blockDim.x) {
        int p = atomicAdd(&g_cursor[dst[i]], 1);
        g_srcsorted[p] = src[i];
    }
}

// ---------------- generic tiled GEMM: C = act((scale*A+shift) @ W^T + bias) ----------------
// A: [nrows, K] with leading dim lda. W: [J, K] row-major. C: [nrows, J] ld ldc.
__global__ void __launch_bounds__(256) gemm_kernel(
    const float* __restrict__ A, int lda,
    const float* __restrict__ W,
    const float* __restrict__ bias,
    const float* __restrict__ scale, const float* __restrict__ shift,
    float* __restrict__ C, int ldc,
    int nrows, int J, int K, int doRelu)
{
    __shared__ float As[32][68];   // [k][m], padded to dodge STS conflicts
    __shared__ float Ws[32][68];   // [k][j]
    int tid = threadIdx.x;
    int tx = tid & 15;             // j-group
    int ty = tid >> 4;             // m-group
    int m0 = blockIdx.x * 64;
    int j0 = blockIdx.y * 64;
    int r = tid >> 3;              // 0..31
    int c = (tid & 7) << 2;        // 0,4,...,28
    ULL acc[2][4] = {};

    for (int k0 = 0; k0 < K; k0 += 32) {
        #pragma unroll
        for (int rr = r; rr < 64; rr += 32) {
            int gm = m0 + rr;
            float v[4] = {0.f, 0.f, 0.f, 0.f};
            if (gm < nrows) {
                const float* ap = A + (size_t)gm * lda + k0 + c;
                #pragma unroll
                for (int i = 0; i < 4; i++) {
                    int k = k0 + c + i;
                    if (k < K) {
                        float a = ap[i];
                        if (scale) a = fmaf(scale[k], a, shift[k]);
                        v[i] = a;
                    }
                }
            }
            #pragma unroll
            for (int i = 0; i < 4; i++) As[c + i][rr] = v[i];
        }
        #pragma unroll
        for (int rr = r; rr < 64; rr += 32) {
            int gj = j0 + rr;
            float v[4] = {0.f, 0.f, 0.f, 0.f};
            if (gj < J) {
                const float* wp = W + (size_t)gj * K + k0 + c;
                #pragma unroll
                for (int i = 0; i < 4; i++) {
                    int k = k0 + c + i;
                    if (k < K) v[i] = wp[i];
                }
            }
            #pragma unroll
            for (int i = 0; i < 4; i++) Ws[c + i][rr] = v[i];
        }
        __syncthreads();
        #pragma unroll
        for (int k = 0; k < 32; k++) {
            const ULL* ap = (const ULL*)&As[k][ty << 2];
            ULL a01 = ap[0];
            ULL a23 = ap[1];
            float4 wv = *(const float4*)&Ws[k][tx << 2];
            ULL b0 = pk2(wv.x, wv.x), b1 = pk2(wv.y, wv.y);
            ULL b2 = pk2(wv.z, wv.z), b3 = pk2(wv.w, wv.w);
            fma2(acc[0][0], a01, b0); fma2(acc[0][1], a01, b1);
            fma2(acc[0][2], a01, b2); fma2(acc[0][3], a01, b3);
            fma2(acc[1][0], a23, b0); fma2(acc[1][1], a23, b1);
            fma2(acc[1][2], a23, b2); fma2(acc[1][3], a23, b3);
        }
        __syncthreads();
    }
    #pragma unroll
    for (int p = 0; p < 2; p++) {
        #pragma unroll
        for (int j = 0; j < 4; j++) {
            float lo, hi;
            upk2(acc[p][j], lo, hi);
            int gj = j0 + (tx << 2) + j;
            if (gj < J) {
                float bv = bias ? bias[gj] : 0.f;
                float v0 = lo + bv, v1 = hi + bv;
                if (doRelu) { v0 = fmaxf(v0, 0.f); v1 = fmaxf(v1, 0.f); }
                int gm0 = m0 + (ty << 2) + 2 * p;
                if (gm0     < nrows) C[(size_t)gm0 * ldc + gj]       = v0;
                if (gm0 + 1 < nrows) C[(size_t)(gm0 + 1) * ldc + gj] = v1;
            }
        }
    }
}

// ---------------- el / er: per-node attention logits ----------------
__global__ void __launch_bounds__(256) elr_kernel(const float* __restrict__ al,
                                                  const float* __restrict__ ar)
{
    int warp = (blockIdx.x * blockDim.x + threadIdx.x) >> 5;
    int lane = threadIdx.x & 31;
    if (warp >= NN) return;
    const float* f = g_feat + (size_t)warp * 128;
    float f0 = f[lane], f1 = f[lane + 32], f2 = f[lane + 64], f3 = f[lane + 96];
    float el0 = f0 * al[lane] + f1 * al[lane + 32];
    float el1 = f2 * al[lane + 64] + f3 * al[lane + 96];
    float er0 = f0 * ar[lane] + f1 * ar[lane + 32];
    float er1 = f2 * ar[lane + 64] + f3 * ar[lane + 96];
    #pragma unroll
    for (int o = 16; o; o >>= 1) {
        el0 += __shfl_xor_sync(~0u, el0, o);
        el1 += __shfl_xor_sync(~0u, el1, o);
        er0 += __shfl_xor_sync(~0u, er0, o);
        er1 += __shfl_xor_sync(~0u, er1, o);
    }
    if (lane == 0) {
        g_el[2 * warp] = el0; g_el[2 * warp + 1] = el1;
        g_er[2 * warp] = er0; g_er[2 * warp + 1] = er1;
    }
}

__device__ __forceinline__ float leaky02(float x) {
    return fmaxf(x, 0.f) + 0.2f * fminf(x, 0.f);
}

// ---------------- GAT edge stage: warp per dst node, CSR-driven ----------------
__global__ void __launch_bounds__(256) gat_edge_kernel(const float* __restrict__ gatb)
{
    int n    = (blockIdx.x * blockDim.x + threadIdx.x) >> 5;
    int lane = threadIdx.x & 31;
    if (n >= NN) return;
    int beg = g_rowptr[n], end = g_rowptr[n + 1];
    int deg = end - beg;
    float er0 = g_er[2 * n], er1 = g_er[2 * n + 1];

    // softmax max
    float m0 = -1e30f, m1 = -1e30f;
    for (int i = lane; i < deg; i += 32) {
        int s = g_srcsorted[beg + i];
        float e0 = leaky02(g_el[2 * s] + er0);
        float e1 = leaky02(g_el[2 * s + 1] + er1);
        m0 = fmaxf(m0, e0); m1 = fmaxf(m1, e1);
    }
    #pragma unroll
    for (int o = 16; o; o >>= 1) {
        m0 = fmaxf(m0, __shfl_xor_sync(~0u, m0, o));
        m1 = fmaxf(m1, __shfl_xor_sync(~0u, m1, o));
    }
    // softmax denom
    float d0 = 0.f, d1 = 0.f;
    for (int i = lane; i < deg; i += 32) {
        int s = g_srcsorted[beg + i];
        float e0 = leaky02(g_el[2 * s] + er0);
        float e1 = leaky02(g_el[2 * s + 1] + er1);
        d0 += __expf(e0 - m0);
        d1 += __expf(e1 - m1);
    }
    #pragma unroll
    for (int o = 16; o; o >>= 1) {
        d0 += __shfl_xor_sync(~0u, d0, o);
        d1 += __shfl_xor_sync(~0u, d1, o);
    }
    float inv0 = (d0 > 0.f) ? 1.f / d0 : 0.f;
    float inv1 = (d1 > 0.f) ? 1.f / d1 : 0.f;

    // weighted aggregation: lane owns 4 dims (lanes 0-15 head0, 16-31 head1)
    int head = lane >> 4;
    float4 acc = make_float4(0.f, 0.f, 0.f, 0.f);
    const float4* feat4 = (const float4*)g_feat;
    for (int cb = 0; cb < deg; cb += 32) {
        int nn2 = min(32, deg - cb);
        int sb = 0; float a0 = 0.f, a1 = 0.f;
        if (lane < nn2) {
            sb = g_srcsorted[beg + cb + lane];
            float e0 = leaky02(g_el[2 * sb] + er0);
            float e1 = leaky02(g_el[2 * sb + 1] + er1);
            a0 = __expf(e0 - m0) * inv0;
            a1 = __expf(e1 - m1) * inv1;
        }
        for (int j = 0; j < nn2; j++) {
            int s    = __shfl_sync(~0u, sb, j);
            float w0 = __shfl_sync(~0u, a0, j);
            float w1 = __shfl_sync(~0u, a1, j);
            float w  = head ? w1 : w0;
            float4 f = feat4[(size_t)s * 32 + lane];
            acc.x = fmaf(w, f.x, acc.x);
            acc.y = fmaf(w, f.y, acc.y);
            acc.z = fmaf(w, f.z, acc.z);
            acc.w = fmaf(w, f.w, acc.w);
        }
    }
    float4 b = ((const float4*)gatb)[lane];
    acc.x += b.x; acc.y += b.y; acc.z += b.z; acc.w += b.w;
    ((float4*)g_gat)[(size_t)n * 32 + lane] = acc;
}

// ---------------- batch-norm column statistics ----------------
__global__ void colstat_kernel(const float* __restrict__ X, int Ccols, int nrows)
{
    int c = threadIdx.x;  // blockDim.x == Ccols
    float s = 0.f, q = 0.f;
    for (int r = blockIdx.x; r < nrows; r += gridDim.x) {
        float v = X[(size_t)r * Ccols + c];
        s += v;
        q = fmaf(v, v, q);
    }
    atomicAdd(&g_stats[c], s);
    atomicAdd(&g_stats[256 + c], q);
}

__global__ void finalize_stats_kernel(const float* __restrict__ gamma,
                                      const float* __restrict__ beta,
                                      int Ccols, float invN)
{
    int c = threadIdx.x;
    if (c < Ccols) {
        float mu  = g_stats[c] * invN;
        float var = g_stats[256 + c] * invN - mu * mu;
        float sc  = gamma[c] * rsqrtf(var + 1e-5f);
        g_scale[c] = sc;
        g_shift[c] = beta[c] - sc * mu;
    }
}

// apply BN2 to ff2 output, store normalized h into the JK concat slice
__global__ void bn_apply_kernel(int colbase)
{
    int idx = blockIdx.x * blockDim.x + threadIdx.x;
    if (idx >= NN * 64) return;
    int nrow = idx >> 6, c = idx & 63;
    g_xs[(size_t)nrow * 256 + colbase + c] = fmaf(g_scale[c], g_mlp[idx], g_shift[c]);
}

// final: out[n] = relu(bn(mlp1_out)) . mlp_w2
__global__ void __launch_bounds__(256) final_kernel(const float* __restrict__ w2,
                                                    float* __restrict__ out)
{
    int n    = (blockIdx.x * blockDim.x + threadIdx.x) >> 5;
    int lane = threadIdx.x & 31;
    if (n >= NN) return;
    const float* t = g_feat + (size_t)n * 64;
    float v = fmaxf(fmaf(g_scale[lane], t[lane], g_shift[lane]), 0.f) * w2[lane]
            + fmaxf(fmaf(g_scale[lane + 32], t[lane + 32], g_shift[lane + 32]), 0.f) * w2[lane + 32];
    #pragma unroll
    for (int o = 16; o; o >>= 1) v += __shfl_xor_sync(~0u, v, o);
    if (lane == 0) out[n] = v;
}

// ---------------- host driver ----------------
extern "C" void kernel_launch(void* const* d_in, const int* in_sizes, int n_in,
                              void* d_out, int out_size)
{
    const float* x       = (const float*)d_in[0];
    const int*   src     = (const int*)d_in[1];
    const int*   dst     = (const int*)d_in[2];
    const float* emb_w   = (const float*)d_in[3];
    const float* emb_b   = (const float*)d_in[4];
    const float* fc_w    = (const float*)d_in[5];
    const float* attn_l  = (const float*)d_in[6];
    const float* attn_r  = (const float*)d_in[7];
    const float* gat_b   = (const float*)d_in[8];
    const float* bn1_g   = (const float*)d_in[9];
    const float* bn1_b   = (const float*)d_in[10];
    const float* ff_w1   = (const float*)d_in[11];
    const float* ff_b1   = (const float*)d_in[12];
    const float* ff_w2   = (const float*)d_in[13];
    const float* ff_b2   = (const float*)d_in[14];
    const float* bn2_g   = (const float*)d_in[15];
    const float* bn2_b   = (const float*)d_in[16];
    const float* mlp_w1  = (const float*)d_in[17];
    const float* mlp_bn_g= (const float*)d_in[18];
    const float* mlp_bn_b= (const float*)d_in[19];
    const float* mlp_w2  = (const float*)d_in[20];
    float* out = (float*)d_out;

    void* p;
    cudaGetSymbolAddress(&p, g_cursor); int*   cur   = (int*)p;
    cudaGetSymbolAddress(&p, g_stats);  float* stats = (float*)p;
    cudaGetSymbolAddress(&p, g_xs);     float* xs    = (float*)p;
    cudaGetSymbolAddress(&p, g_feat);   float* feat  = (float*)p;
    cudaGetSymbolAddress(&p, g_gat);    float* gat   = (float*)p;
    cudaGetSymbolAddress(&p, g_ff);     float* ffb   = (float*)p;
    cudaGetSymbolAddress(&p, g_mlp);    float* mlpb  = (float*)p;
    cudaGetSymbolAddress(&p, g_scale);  float* sc    = (float*)p;
    cudaGetSymbolAddress(&p, g_shift);  float* sh    = (float*)p;

    const int GX = (NN + 63) / 64;          // 782
    const int WG = (NN * 32 + 255) / 256;   // 6250 (warp-per-node kernels)
    const float invN = 1.f / (float)NN;

    // CSR build (by dst)
    cudaMemsetAsync(cur, 0, NN * sizeof(int));
    hist_kernel<<<2048, 256>>>(dst);
    scan_kernel<<<1, 1024>>>();
    scatter_kernel<<<2048, 256>>>(src, dst);

    // embedding: xs[:, 0:64] = x @ emb_w^T + emb_b
    gemm_kernel<<<dim3(GX, 1), 256>>>(x, 64, emb_w, emb_b, nullptr, nullptr,
                                      xs, 256, NN, 64, 64, 0);

    for (int l = 0; l < LAYERS; l++) {
        const float* h = xs + l * 64;  // lda 256
        // feat = h @ fc_w[l]^T
        gemm_kernel<<<dim3(GX, 2), 256>>>(h, 256, fc_w + (size_t)l * 128 * 64,
                                          nullptr, nullptr, nullptr,
                                          feat, 128, NN, 128, 64, 0);
        elr_kernel<<<WG, 256>>>(attn_l + l * 128, attn_r + l * 128);
        gat_edge_kernel<<<WG, 256>>>(gat_b + l * 128);

        // BN1 stats -> scale/shift (folded into ff1 input)
        cudaMemsetAsync(stats, 0, 512 * sizeof(float));
        colstat_kernel<<<128, 128>>>(gat, 128, NN);
        finalize_stats_kernel<<<1, 128>>>(bn1_g + l * 128, bn1_b + l * 128, 128, invN);

        // ff1: relu(bn1(gat) @ ff_w1^T + b1)
        gemm_kernel<<<dim3(GX, 4), 256>>>(gat, 128, ff_w1 + (size_t)l * FF * 128,
                                          ff_b1 + l * FF, sc, sh,
                                          ffb, FFP, NN, FF, 128, 1);
        // ff2
        gemm_kernel<<<dim3(GX, 1), 256>>>(ffb, FFP, ff_w2 + (size_t)l * 64 * FF,
                                          ff_b2 + l * 64, nullptr, nullptr,
                                          mlpb, 64, NN, 64, FF, 0);
        // BN2 -> h stored into xs[:, (l+1)*64 : ]
        cudaMemsetAsync(stats, 0, 512 * sizeof(float));
        colstat_kernel<<<128, 64>>>(mlpb, 64, NN);
        finalize_stats_kernel<<<1, 64>>>(bn2_g + l * 64, bn2_b + l * 64, 64, invN);
        bn_apply_kernel<<<(NN * 64 + 255) / 256, 256>>>((l + 1) * 64);
    }

    // MLP head: t = xs @ mlp_w1^T ; out = relu(bn(t)) @ mlp_w2^T
    gemm_kernel<<<dim3(GX, 1), 256>>>(xs, 256, mlp_w1, nullptr, nullptr, nullptr,
                                      feat, 64, NN, 64, 256, 0);
    cudaMemsetAsync(stats, 0, 512 * sizeof(float));
    colstat_kernel<<<128, 64>>>(feat, 64, NN);
    finalize_stats_kernel<<<1, 64>>>(mlp_bn_g, mlp_bn_b, 64, invN);
    final_kernel<<<WG, 256>>>(mlp_w2, out);

    (void)in_sizes; (void)n_in; (void)out_size;
}